// round 9
// baseline (speedup 1.0000x reference)
#include <cuda_runtime.h>
#include <cuda_bf16.h>

// Problem constants
#define T_DIM 8
#define C_DIM 3
#define HW    65536   // 256*256
#define NPIX  262144  // B(4) * HW

// ---------------- packed f32x2 helpers (Blackwell) ----------------
typedef unsigned long long f32x2;

__device__ __forceinline__ f32x2 pack2(float lo, float hi) {
    f32x2 r; asm("mov.b64 %0, {%1, %2};" : "=l"(r) : "f"(lo), "f"(hi)); return r;
}
__device__ __forceinline__ void unpack2(f32x2 v, float& lo, float& hi) {
    asm("mov.b64 {%0, %1}, %2;" : "=f"(lo), "=f"(hi) : "l"(v));
}
__device__ __forceinline__ f32x2 fma2(f32x2 a, f32x2 b, f32x2 c) {
    f32x2 d; asm("fma.rn.f32x2 %0, %1, %2, %3;" : "=l"(d) : "l"(a), "l"(b), "l"(c)); return d;
}
__device__ __forceinline__ f32x2 add2(f32x2 a, f32x2 b) {
    f32x2 d; asm("add.rn.f32x2 %0, %1, %2;" : "=l"(d) : "l"(a), "l"(b)); return d;
}
__device__ __forceinline__ f32x2 mul2(f32x2 a, f32x2 b) {
    f32x2 d; asm("mul.rn.f32x2 %0, %1, %2;" : "=l"(d) : "l"(a), "l"(b)); return d;
}
__device__ __forceinline__ f32x2 ex2_2(f32x2 v) {
    float lo, hi; unpack2(v, lo, hi);
    float el, eh;
    asm("ex2.approx.ftz.f32 %0, %1;" : "=f"(el) : "f"(lo));
    asm("ex2.approx.ftz.f32 %0, %1;" : "=f"(eh) : "f"(hi));
    return pack2(el, eh);
}
__device__ __forceinline__ f32x2 rcp_2(f32x2 v) {
    float lo, hi; unpack2(v, lo, hi);
    float rl, rh;
    asm("rcp.approx.ftz.f32 %0, %1;" : "=f"(rl) : "f"(lo));
    asm("rcp.approx.ftz.f32 %0, %1;" : "=f"(rh) : "f"(hi));
    return pack2(rl, rh);
}

// Fused kernel, 128 threads/block, 2 pixels/thread, NATURAL register allocation
// (no occupancy clamp — R3's 64-reg cap spilled zv to local memory).
//
// Key scheduling trick: all 24 global loads are issued BEFORE the per-block
// weight-folding phase, so DRAM latency is hidden behind the setup compute.
//
// Folded constants (score path pre-scaled by 1/sqrt(8)*log2(e) for raw ex2):
//   per head n (25): MT[3][3], u[3], g[3], c, P[3][3]
//   [100..102] output bias p
__global__ void __launch_bounds__(128)
fused_kernel(const float* __restrict__ z, float* __restrict__ out,
             const float* __restrict__ W_in, const float* __restrict__ b_in,
             const float* __restrict__ W_q,  const float* __restrict__ b_q,
             const float* __restrict__ W_k,  const float* __restrict__ b_k,
             const float* __restrict__ W_v,  const float* __restrict__ b_v,
             const float* __restrict__ W_o,  const float* __restrict__ b_o) {
    __shared__ float A[32][3], Bm[32][3], Cm[32][3];
    __shared__ float aQ[32], bK[32], cV[32];
    __shared__ f32x2 cst[103];

    int tid = threadIdx.x;  // 128 threads

    // ---- issue pixel loads FIRST (independent of setup; hides DRAM latency) ----
    int gid = blockIdx.x * 128 + tid;
    int pix = gid << 1;
    int b  = pix >> 16;
    int hw = pix & (HW - 1);
    const float* zp = z + (size_t)b * (T_DIM * C_DIM * HW) + hw;

    f32x2 zv[24];                           // [t*3 + c], each holds 2 pixels
    #pragma unroll
    for (int i = 0; i < 24; i++)
        zv[i] = *reinterpret_cast<const f32x2*>(zp + (size_t)i * HW);

    // ---- setup phase 1: A = W_q@W_in etc. (384 tasks over 128 threads) ----
    for (int task = tid; task < 384; task += 128) {
        int m = task >> 7;
        int r = task & 127;
        const float* Wm = (m == 0) ? W_q : (m == 1) ? W_k : W_v;
        const float* bm = (m == 0) ? b_q : (m == 1) ? b_k : b_v;
        if (r < 96) {
            int o = r / 3, i = r - 3 * o;
            float s = 0.f;
            #pragma unroll
            for (int j = 0; j < 32; j++) s += Wm[o * 32 + j] * W_in[j * 3 + i];
            if (m == 0) A[o][i] = s; else if (m == 1) Bm[o][i] = s; else Cm[o][i] = s;
        } else {
            int o = r - 96;
            float s = bm[o];
            #pragma unroll
            for (int j = 0; j < 32; j++) s += Wm[o * 32 + j] * b_in[j];
            if (m == 0) aQ[o] = s; else if (m == 1) bK[o] = s; else cV[o] = s;
        }
    }
    __syncthreads();

    // ---- setup phase 2: fold into 103 constants ----
    const float scale = 0.3535533905932738f * 1.4426950408889634f;  // 1/sqrt(8)*log2(e)
    if (tid < 103) {
        float s = 0.f;
        if (tid >= 100) {
            int o = tid - 100;
            s = b_o[o];
            #pragma unroll
            for (int r = 0; r < 32; r++) s += W_o[o * 32 + r] * cV[r];
        } else {
            int n = tid / 25, k = tid - 25 * n;
            int base = n * 8;
            if (k < 9) {
                int j = k / 3, i = k - 3 * j;
                #pragma unroll
                for (int d = 0; d < 8; d++) s += A[base + d][i] * Bm[base + d][j];
                s *= scale;
            } else if (k < 12) {
                int j = k - 9;
                #pragma unroll
                for (int d = 0; d < 8; d++) s += aQ[base + d] * Bm[base + d][j];
                s *= scale;
            } else if (k < 15) {
                int i = k - 12;
                #pragma unroll
                for (int d = 0; d < 8; d++) s += A[base + d][i] * bK[base + d];
                s *= scale;
            } else if (k == 15) {
                #pragma unroll
                for (int d = 0; d < 8; d++) s += aQ[base + d] * bK[base + d];
                s *= scale;
            } else {
                int kk = k - 16;
                int o = kk / 3, i = kk - 3 * o;
                #pragma unroll
                for (int d = 0; d < 8; d++) s += W_o[o * 32 + base + d] * Cm[base + d][i];
            }
        }
        cst[tid] = pack2(s, s);
    }
    __syncthreads();

    // ---- main phase: packed f32x2 attention ----
    f32x2 z70 = zv[21], z71 = zv[22], z72 = zv[23];
    f32x2 o0 = cst[100], o1 = cst[101], o2 = cst[102];

    #pragma unroll
    for (int n = 0; n < 4; n++) {
        const f32x2* cs = cst + n * 25;
        f32x2 r0 = fma2(cs[0], z70, fma2(cs[1], z71, fma2(cs[2], z72, cs[9])));
        f32x2 r1 = fma2(cs[3], z70, fma2(cs[4], z71, fma2(cs[5], z72, cs[10])));
        f32x2 r2 = fma2(cs[6], z70, fma2(cs[7], z71, fma2(cs[8], z72, cs[11])));
        f32x2 s  = fma2(cs[12], z70, fma2(cs[13], z71, fma2(cs[14], z72, cs[15])));

        f32x2 esum = 0ULL, zb0 = 0ULL, zb1 = 0ULL, zb2 = 0ULL;
        #pragma unroll
        for (int t = 0; t < T_DIM; t++) {
            f32x2 a0 = zv[t * 3], a1 = zv[t * 3 + 1], a2 = zv[t * 3 + 2];
            f32x2 sc = fma2(r0, a0, fma2(r1, a1, fma2(r2, a2, s)));
            f32x2 e  = ex2_2(sc);   // scores tiny: no max-subtraction needed
            esum = add2(esum, e);
            zb0 = fma2(e, a0, zb0);
            zb1 = fma2(e, a1, zb1);
            zb2 = fma2(e, a2, zb2);
        }
        f32x2 inv = rcp_2(esum);
        zb0 = mul2(zb0, inv); zb1 = mul2(zb1, inv); zb2 = mul2(zb2, inv);
        o0 = fma2(cs[16], zb0, fma2(cs[17], zb1, fma2(cs[18], zb2, o0)));
        o1 = fma2(cs[19], zb0, fma2(cs[20], zb1, fma2(cs[21], zb2, o1)));
        o2 = fma2(cs[22], zb0, fma2(cs[23], zb1, fma2(cs[24], zb2, o2)));
    }

    float* op = out + (size_t)b * (3 * HW) + hw;
    *reinterpret_cast<f32x2*>(op)          = o0;
    *reinterpret_cast<f32x2*>(op + HW)     = o1;
    *reinterpret_cast<f32x2*>(op + 2 * HW) = o2;
}

extern "C" void kernel_launch(void* const* d_in, const int* in_sizes, int n_in,
                              void* d_out, int out_size) {
    const float* z    = (const float*)d_in[0];
    const float* W_in = (const float*)d_in[1];
    const float* b_in = (const float*)d_in[2];
    const float* W_q  = (const float*)d_in[3];
    const float* b_q  = (const float*)d_in[4];
    const float* W_k  = (const float*)d_in[5];
    const float* b_k  = (const float*)d_in[6];
    const float* W_v  = (const float*)d_in[7];
    const float* b_v  = (const float*)d_in[8];
    const float* W_o  = (const float*)d_in[9];
    const float* b_o  = (const float*)d_in[10];
    float* out = (float*)d_out;

    fused_kernel<<<NPIX / 256, 128>>>(z, out,
                                      W_in, b_in, W_q, b_q, W_k, b_k,
                                      W_v, b_v, W_o, b_o);
}

// round 11
// speedup vs baseline: 1.0827x; 1.0827x over previous
#include <cuda_runtime.h>
#include <cuda_bf16.h>

// Problem constants
#define T_DIM 8
#define C_DIM 3
#define HW    65536   // 256*256
#define NPIX  262144  // B(4) * HW

// ---------------- packed f32x2 helpers (Blackwell) ----------------
typedef unsigned long long f32x2;

__device__ __forceinline__ f32x2 pack2(float lo, float hi) {
    f32x2 r; asm("mov.b64 %0, {%1, %2};" : "=l"(r) : "f"(lo), "f"(hi)); return r;
}
__device__ __forceinline__ void unpack2(f32x2 v, float& lo, float& hi) {
    asm("mov.b64 {%0, %1}, %2;" : "=f"(lo), "=f"(hi) : "l"(v));
}
__device__ __forceinline__ f32x2 fma2(f32x2 a, f32x2 b, f32x2 c) {
    f32x2 d; asm("fma.rn.f32x2 %0, %1, %2, %3;" : "=l"(d) : "l"(a), "l"(b), "l"(c)); return d;
}
__device__ __forceinline__ f32x2 add2(f32x2 a, f32x2 b) {
    f32x2 d; asm("add.rn.f32x2 %0, %1, %2;" : "=l"(d) : "l"(a), "l"(b)); return d;
}
__device__ __forceinline__ f32x2 mul2(f32x2 a, f32x2 b) {
    f32x2 d; asm("mul.rn.f32x2 %0, %1, %2;" : "=l"(d) : "l"(a), "l"(b)); return d;
}
__device__ __forceinline__ f32x2 ex2_2(f32x2 v) {
    float lo, hi; unpack2(v, lo, hi);
    float el, eh;
    asm("ex2.approx.ftz.f32 %0, %1;" : "=f"(el) : "f"(lo));
    asm("ex2.approx.ftz.f32 %0, %1;" : "=f"(eh) : "f"(hi));
    return pack2(el, eh);
}
__device__ __forceinline__ f32x2 rcp_2(f32x2 v) {
    float lo, hi; unpack2(v, lo, hi);
    float rl, rh;
    asm("rcp.approx.ftz.f32 %0, %1;" : "=f"(rl) : "f"(lo));
    asm("rcp.approx.ftz.f32 %0, %1;" : "=f"(rh) : "f"(hi));
    return pack2(rl, rh);
}

// Fused kernel: SETUP FIRST, pixel loads AFTER (critical ordering — keeping the
// 48-reg zv payload live across the setup phase is what spilled R3/R4).
// After the last __syncthreads the register environment matches the clean
// two-kernel attn body (80 regs, no spills).
__global__ void __launch_bounds__(128)
fused_kernel(const float* __restrict__ z, float* __restrict__ out,
             const float* __restrict__ W_in, const float* __restrict__ b_in,
             const float* __restrict__ W_q,  const float* __restrict__ b_q,
             const float* __restrict__ W_k,  const float* __restrict__ b_k,
             const float* __restrict__ W_v,  const float* __restrict__ b_v,
             const float* __restrict__ W_o,  const float* __restrict__ b_o) {
    __shared__ float A[32][3], Bm[32][3], Cm[32][3];
    __shared__ float aQ[32], bK[32], cV[32];
    __shared__ f32x2 cst[103];

    int tid = threadIdx.x;  // 128 threads

    // ---- setup phase 1: A = W_q@W_in etc. (384 tasks over 128 threads) ----
    for (int task = tid; task < 384; task += 128) {
        int m = task >> 7;
        int r = task & 127;
        const float* Wm = (m == 0) ? W_q : (m == 1) ? W_k : W_v;
        const float* bm = (m == 0) ? b_q : (m == 1) ? b_k : b_v;
        if (r < 96) {
            int o = r / 3, i = r - 3 * o;
            float s = 0.f;
            #pragma unroll
            for (int j = 0; j < 32; j++) s += Wm[o * 32 + j] * W_in[j * 3 + i];
            if (m == 0) A[o][i] = s; else if (m == 1) Bm[o][i] = s; else Cm[o][i] = s;
        } else {
            int o = r - 96;
            float s = bm[o];
            #pragma unroll
            for (int j = 0; j < 32; j++) s += Wm[o * 32 + j] * b_in[j];
            if (m == 0) aQ[o] = s; else if (m == 1) bK[o] = s; else cV[o] = s;
        }
    }
    __syncthreads();

    // ---- setup phase 2: fold into 103 constants ----
    const float scale = 0.3535533905932738f * 1.4426950408889634f;  // 1/sqrt(8)*log2(e)
    if (tid < 103) {
        float s = 0.f;
        if (tid >= 100) {
            int o = tid - 100;
            s = b_o[o];
            #pragma unroll
            for (int r = 0; r < 32; r++) s += W_o[o * 32 + r] * cV[r];
        } else {
            int n = tid / 25, k = tid - 25 * n;
            int base = n * 8;
            if (k < 9) {
                int j = k / 3, i = k - 3 * j;
                #pragma unroll
                for (int d = 0; d < 8; d++) s += A[base + d][i] * Bm[base + d][j];
                s *= scale;
            } else if (k < 12) {
                int j = k - 9;
                #pragma unroll
                for (int d = 0; d < 8; d++) s += aQ[base + d] * Bm[base + d][j];
                s *= scale;
            } else if (k < 15) {
                int i = k - 12;
                #pragma unroll
                for (int d = 0; d < 8; d++) s += A[base + d][i] * bK[base + d];
                s *= scale;
            } else if (k == 15) {
                #pragma unroll
                for (int d = 0; d < 8; d++) s += aQ[base + d] * bK[base + d];
                s *= scale;
            } else {
                int kk = k - 16;
                int o = kk / 3, i = kk - 3 * o;
                #pragma unroll
                for (int d = 0; d < 8; d++) s += W_o[o * 32 + base + d] * Cm[base + d][i];
            }
        }
        cst[tid] = pack2(s, s);
    }
    __syncthreads();

    // Compiler fence: do NOT hoist the pixel loads up into the setup phase —
    // that extends zv's live range across setup and spills (R3/R4 failure).
    asm volatile("" ::: "memory");

    // ---- main phase: 2 pixels per thread, packed f32x2 ----
    int gid = blockIdx.x * 128 + tid;
    int pix = gid << 1;
    int b  = pix >> 16;
    int hw = pix & (HW - 1);
    const float* zp = z + (size_t)b * (T_DIM * C_DIM * HW) + hw;

    f32x2 zv[24];                           // [t*3 + c], each holds 2 pixels
    #pragma unroll
    for (int i = 0; i < 24; i++)
        zv[i] = *reinterpret_cast<const f32x2*>(zp + (size_t)i * HW);

    f32x2 z70 = zv[21], z71 = zv[22], z72 = zv[23];
    f32x2 o0 = cst[100], o1 = cst[101], o2 = cst[102];

    #pragma unroll
    for (int n = 0; n < 4; n++) {
        const f32x2* cs = cst + n * 25;
        f32x2 r0 = fma2(cs[0], z70, fma2(cs[1], z71, fma2(cs[2], z72, cs[9])));
        f32x2 r1 = fma2(cs[3], z70, fma2(cs[4], z71, fma2(cs[5], z72, cs[10])));
        f32x2 r2 = fma2(cs[6], z70, fma2(cs[7], z71, fma2(cs[8], z72, cs[11])));
        f32x2 s  = fma2(cs[12], z70, fma2(cs[13], z71, fma2(cs[14], z72, cs[15])));

        f32x2 esum = 0ULL, zb0 = 0ULL, zb1 = 0ULL, zb2 = 0ULL;
        #pragma unroll
        for (int t = 0; t < T_DIM; t++) {
            f32x2 a0 = zv[t * 3], a1 = zv[t * 3 + 1], a2 = zv[t * 3 + 2];
            f32x2 sc = fma2(r0, a0, fma2(r1, a1, fma2(r2, a2, s)));
            f32x2 e  = ex2_2(sc);   // scores tiny: no max-subtraction needed
            esum = add2(esum, e);
            zb0 = fma2(e, a0, zb0);
            zb1 = fma2(e, a1, zb1);
            zb2 = fma2(e, a2, zb2);
        }
        f32x2 inv = rcp_2(esum);
        zb0 = mul2(zb0, inv); zb1 = mul2(zb1, inv); zb2 = mul2(zb2, inv);
        o0 = fma2(cs[16], zb0, fma2(cs[17], zb1, fma2(cs[18], zb2, o0)));
        o1 = fma2(cs[19], zb0, fma2(cs[20], zb1, fma2(cs[21], zb2, o1)));
        o2 = fma2(cs[22], zb0, fma2(cs[23], zb1, fma2(cs[24], zb2, o2)));
    }

    float* op = out + (size_t)b * (3 * HW) + hw;
    *reinterpret_cast<f32x2*>(op)          = o0;
    *reinterpret_cast<f32x2*>(op + HW)     = o1;
    *reinterpret_cast<f32x2*>(op + 2 * HW) = o2;
}

extern "C" void kernel_launch(void* const* d_in, const int* in_sizes, int n_in,
                              void* d_out, int out_size) {
    const float* z    = (const float*)d_in[0];
    const float* W_in = (const float*)d_in[1];
    const float* b_in = (const float*)d_in[2];
    const float* W_q  = (const float*)d_in[3];
    const float* b_q  = (const float*)d_in[4];
    const float* W_k  = (const float*)d_in[5];
    const float* b_k  = (const float*)d_in[6];
    const float* W_v  = (const float*)d_in[7];
    const float* b_v  = (const float*)d_in[8];
    const float* W_o  = (const float*)d_in[9];
    const float* b_o  = (const float*)d_in[10];
    float* out = (float*)d_out;

    fused_kernel<<<NPIX / 256, 128>>>(z, out,
                                      W_in, b_in, W_q, b_q, W_k, b_k,
                                      W_v, b_v, W_o, b_o);
}

// round 12
// speedup vs baseline: 2.5563x; 2.3609x over previous
#include <cuda_runtime.h>
#include <cuda_bf16.h>

// Problem constants
#define T_DIM 8
#define C_DIM 3
#define HW    65536   // 256*256
#define NPIX  262144  // B(4) * HW

// ---------------- packed f32x2 helpers (Blackwell) ----------------
typedef unsigned long long f32x2;

__device__ __forceinline__ f32x2 pack2(float lo, float hi) {
    f32x2 r; asm("mov.b64 %0, {%1, %2};" : "=l"(r) : "f"(lo), "f"(hi)); return r;
}
__device__ __forceinline__ void unpack2(f32x2 v, float& lo, float& hi) {
    asm("mov.b64 {%0, %1}, %2;" : "=f"(lo), "=f"(hi) : "l"(v));
}
__device__ __forceinline__ f32x2 fma2(f32x2 a, f32x2 b, f32x2 c) {
    f32x2 d; asm("fma.rn.f32x2 %0, %1, %2, %3;" : "=l"(d) : "l"(a), "l"(b), "l"(c)); return d;
}
__device__ __forceinline__ f32x2 add2(f32x2 a, f32x2 b) {
    f32x2 d; asm("add.rn.f32x2 %0, %1, %2;" : "=l"(d) : "l"(a), "l"(b)); return d;
}
__device__ __forceinline__ f32x2 mul2(f32x2 a, f32x2 b) {
    f32x2 d; asm("mul.rn.f32x2 %0, %1, %2;" : "=l"(d) : "l"(a), "l"(b)); return d;
}
__device__ __forceinline__ f32x2 ex2_2(f32x2 v) {
    float lo, hi; unpack2(v, lo, hi);
    float el, eh;
    asm("ex2.approx.ftz.f32 %0, %1;" : "=f"(el) : "f"(lo));
    asm("ex2.approx.ftz.f32 %0, %1;" : "=f"(eh) : "f"(hi));
    return pack2(el, eh);
}
__device__ __forceinline__ f32x2 rcp_2(f32x2 v) {
    float lo, hi; unpack2(v, lo, hi);
    float rl, rh;
    asm("rcp.approx.ftz.f32 %0, %1;" : "=f"(rl) : "f"(lo));
    asm("rcp.approx.ftz.f32 %0, %1;" : "=f"(rh) : "f"(hi));
    return pack2(rl, rh);
}

#define WPAD 33   // 32 + 1 padding: bank(o*33+j) = (o+j)%32 -> conflict-free

// Fused kernel. Setup phase rebuilt to be L1-clean:
//  - coalesced staging of ALL weights into shared (27 LDG.32/thread)
//  - fold dot-products read shared with padded rows (no bank conflicts)
//  - main phase identical to the proven R2 attention body.
__global__ void __launch_bounds__(128)
fused_kernel(const float* __restrict__ z, float* __restrict__ out,
             const float* __restrict__ W_in, const float* __restrict__ b_in,
             const float* __restrict__ W_q,  const float* __restrict__ b_q,
             const float* __restrict__ W_k,  const float* __restrict__ b_k,
             const float* __restrict__ W_v,  const float* __restrict__ b_v,
             const float* __restrict__ W_o,  const float* __restrict__ b_o) {
    __shared__ float Wqs[32 * WPAD], Wks[32 * WPAD], Wvs[32 * WPAD];
    __shared__ float Wis[96], Wos[96];
    __shared__ float bis[32], bqs[32], bks[32], bvs[32], bos[3];
    __shared__ float A[32][3], Bm[32][3], Cm[32][3];
    __shared__ float aQ[32], bK[32], cV[32];
    __shared__ f32x2 cst[103];

    int tid = threadIdx.x;  // 128 threads

    // ---- stage weights into shared, fully coalesced ----
    #pragma unroll
    for (int p = 0; p < 8; p++) {
        int idx = p * 128 + tid;           // 0..1023
        int o = idx >> 5, j = idx & 31;
        Wqs[o * WPAD + j] = W_q[idx];
        Wks[o * WPAD + j] = W_k[idx];
        Wvs[o * WPAD + j] = W_v[idx];
    }
    if (tid < 96) { Wis[tid] = W_in[tid]; Wos[tid] = W_o[tid]; }
    if (tid < 32) { bis[tid] = b_in[tid]; bqs[tid] = b_q[tid];
                    bks[tid] = b_k[tid];  bvs[tid] = b_v[tid]; }
    if (tid < 3)  { bos[tid] = b_o[tid]; }
    __syncthreads();

    // ---- setup phase 1: A = W_q@W_in etc. (3 tasks/thread, shared reads) ----
    #pragma unroll
    for (int m = 0; m < 3; m++) {
        const float* Wm = (m == 0) ? Wqs : (m == 1) ? Wks : Wvs;
        const float* bm = (m == 0) ? bqs : (m == 1) ? bks : bvs;
        if (tid < 96) {
            int o = tid & 31, i = tid >> 5;   // lanes walk consecutive rows o
            float s = 0.f;
            #pragma unroll
            for (int j = 0; j < 32; j++) s += Wm[o * WPAD + j] * Wis[j * 3 + i];
            if (m == 0) A[o][i] = s; else if (m == 1) Bm[o][i] = s; else Cm[o][i] = s;
        } else {
            int o = tid - 96;
            float s = bm[o];
            #pragma unroll
            for (int j = 0; j < 32; j++) s += Wm[o * WPAD + j] * bis[j];
            if (m == 0) aQ[o] = s; else if (m == 1) bK[o] = s; else cV[o] = s;
        }
    }
    __syncthreads();

    // ---- setup phase 2: fold into 103 constants (all-shared reads) ----
    const float scale = 0.3535533905932738f * 1.4426950408889634f;  // 1/sqrt(8)*log2(e)
    if (tid < 103) {
        float s = 0.f;
        if (tid >= 100) {
            int o = tid - 100;
            s = bos[o];
            #pragma unroll
            for (int r = 0; r < 32; r++) s += Wos[o * 32 + r] * cV[r];
        } else {
            int n = tid / 25, k = tid - 25 * n;
            int base = n * 8;
            if (k < 9) {
                int j = k / 3, i = k - 3 * j;
                #pragma unroll
                for (int d = 0; d < 8; d++) s += A[base + d][i] * Bm[base + d][j];
                s *= scale;
            } else if (k < 12) {
                int j = k - 9;
                #pragma unroll
                for (int d = 0; d < 8; d++) s += aQ[base + d] * Bm[base + d][j];
                s *= scale;
            } else if (k < 15) {
                int i = k - 12;
                #pragma unroll
                for (int d = 0; d < 8; d++) s += A[base + d][i] * bK[base + d];
                s *= scale;
            } else if (k == 15) {
                #pragma unroll
                for (int d = 0; d < 8; d++) s += aQ[base + d] * bK[base + d];
                s *= scale;
            } else {
                int kk = k - 16;
                int o = kk / 3, i = kk - 3 * o;
                #pragma unroll
                for (int d = 0; d < 8; d++) s += Wos[o * 32 + base + d] * Cm[base + d][i];
            }
        }
        cst[tid] = pack2(s, s);
    }
    __syncthreads();

    // Fence: keep zv loads below the setup phase (live-range containment).
    asm volatile("" ::: "memory");

    // ---- main phase: 2 pixels per thread, packed f32x2 (R2 body) ----
    int gid = blockIdx.x * 128 + tid;
    int pix = gid << 1;
    int b  = pix >> 16;
    int hw = pix & (HW - 1);
    const float* zp = z + (size_t)b * (T_DIM * C_DIM * HW) + hw;

    f32x2 zv[24];
    #pragma unroll
    for (int i = 0; i < 24; i++)
        zv[i] = *reinterpret_cast<const f32x2*>(zp + (size_t)i * HW);

    f32x2 z70 = zv[21], z71 = zv[22], z72 = zv[23];
    f32x2 o0 = cst[100], o1 = cst[101], o2 = cst[102];

    #pragma unroll
    for (int n = 0; n < 4; n++) {
        const f32x2* cs = cst + n * 25;
        f32x2 r0 = fma2(cs[0], z70, fma2(cs[1], z71, fma2(cs[2], z72, cs[9])));
        f32x2 r1 = fma2(cs[3], z70, fma2(cs[4], z71, fma2(cs[5], z72, cs[10])));
        f32x2 r2 = fma2(cs[6], z70, fma2(cs[7], z71, fma2(cs[8], z72, cs[11])));
        f32x2 s  = fma2(cs[12], z70, fma2(cs[13], z71, fma2(cs[14], z72, cs[15])));

        f32x2 esum = 0ULL, zb0 = 0ULL, zb1 = 0ULL, zb2 = 0ULL;
        #pragma unroll
        for (int t = 0; t < T_DIM; t++) {
            f32x2 a0 = zv[t * 3], a1 = zv[t * 3 + 1], a2 = zv[t * 3 + 2];
            f32x2 sc = fma2(r0, a0, fma2(r1, a1, fma2(r2, a2, s)));
            f32x2 e  = ex2_2(sc);   // scores tiny: no max-subtraction needed
            esum = add2(esum, e);
            zb0 = fma2(e, a0, zb0);
            zb1 = fma2(e, a1, zb1);
            zb2 = fma2(e, a2, zb2);
        }
        f32x2 inv = rcp_2(esum);
        zb0 = mul2(zb0, inv); zb1 = mul2(zb1, inv); zb2 = mul2(zb2, inv);
        o0 = fma2(cs[16], zb0, fma2(cs[17], zb1, fma2(cs[18], zb2, o0)));
        o1 = fma2(cs[19], zb0, fma2(cs[20], zb1, fma2(cs[21], zb2, o1)));
        o2 = fma2(cs[22], zb0, fma2(cs[23], zb1, fma2(cs[24], zb2, o2)));
    }

    float* op = out + (size_t)b * (3 * HW) + hw;
    *reinterpret_cast<f32x2*>(op)          = o0;
    *reinterpret_cast<f32x2*>(op + HW)     = o1;
    *reinterpret_cast<f32x2*>(op + 2 * HW) = o2;
}

extern "C" void kernel_launch(void* const* d_in, const int* in_sizes, int n_in,
                              void* d_out, int out_size) {
    const float* z    = (const float*)d_in[0];
    const float* W_in = (const float*)d_in[1];
    const float* b_in = (const float*)d_in[2];
    const float* W_q  = (const float*)d_in[3];
    const float* b_q  = (const float*)d_in[4];
    const float* W_k  = (const float*)d_in[5];
    const float* b_k  = (const float*)d_in[6];
    const float* W_v  = (const float*)d_in[7];
    const float* b_v  = (const float*)d_in[8];
    const float* W_o  = (const float*)d_in[9];
    const float* b_o  = (const float*)d_in[10];
    float* out = (float*)d_out;

    fused_kernel<<<NPIX / 256, 128>>>(z, out,
                                      W_in, b_in, W_q, b_q, W_k, b_k,
                                      W_v, b_v, W_o, b_o);
}

// round 13
// speedup vs baseline: 2.5948x; 1.0151x over previous
#include <cuda_runtime.h>
#include <cuda_bf16.h>

// Problem constants
#define T_DIM 8
#define C_DIM 3
#define HW    65536   // 256*256
#define NPIX  262144  // B(4) * HW
#define NPAIR 131072  // NPIX/2
#define NTHREADS_TOTAL 65536   // 512 blocks * 128 threads; 2 pairs per thread

// ---------------- packed f32x2 helpers (Blackwell) ----------------
typedef unsigned long long f32x2;

__device__ __forceinline__ f32x2 pack2(float lo, float hi) {
    f32x2 r; asm("mov.b64 %0, {%1, %2};" : "=l"(r) : "f"(lo), "f"(hi)); return r;
}
__device__ __forceinline__ void unpack2(f32x2 v, float& lo, float& hi) {
    asm("mov.b64 {%0, %1}, %2;" : "=f"(lo), "=f"(hi) : "l"(v));
}
__device__ __forceinline__ f32x2 fma2(f32x2 a, f32x2 b, f32x2 c) {
    f32x2 d; asm("fma.rn.f32x2 %0, %1, %2, %3;" : "=l"(d) : "l"(a), "l"(b), "l"(c)); return d;
}
__device__ __forceinline__ f32x2 add2(f32x2 a, f32x2 b) {
    f32x2 d; asm("add.rn.f32x2 %0, %1, %2;" : "=l"(d) : "l"(a), "l"(b)); return d;
}
__device__ __forceinline__ f32x2 mul2(f32x2 a, f32x2 b) {
    f32x2 d; asm("mul.rn.f32x2 %0, %1, %2;" : "=l"(d) : "l"(a), "l"(b)); return d;
}
__device__ __forceinline__ f32x2 ex2_2(f32x2 v) {
    float lo, hi; unpack2(v, lo, hi);
    float el, eh;
    asm("ex2.approx.ftz.f32 %0, %1;" : "=f"(el) : "f"(lo));
    asm("ex2.approx.ftz.f32 %0, %1;" : "=f"(eh) : "f"(hi));
    return pack2(el, eh);
}
__device__ __forceinline__ f32x2 rcp_2(f32x2 v) {
    float lo, hi; unpack2(v, lo, hi);
    float rl, rh;
    asm("rcp.approx.ftz.f32 %0, %1;" : "=f"(rl) : "f"(lo));
    asm("rcp.approx.ftz.f32 %0, %1;" : "=f"(rh) : "f"(hi));
    return pack2(rl, rh);
}
__device__ __forceinline__ void prefetch_l2(const void* p) {
    asm volatile("prefetch.global.L2 [%0];" :: "l"(p));
}

#define WPAD 33   // 32 + 1 padding: bank(o*33+j) = (o+j)%32 -> conflict-free

// ---- the attention body for one pixel-pair (pure function of zv + cst) ----
__device__ __forceinline__ void attn_pair(const float* __restrict__ zp,
                                          float* __restrict__ op,
                                          const f32x2* __restrict__ cst) {
    f32x2 zv[24];
    #pragma unroll
    for (int i = 0; i < 24; i++)
        zv[i] = *reinterpret_cast<const f32x2*>(zp + (size_t)i * HW);

    f32x2 z70 = zv[21], z71 = zv[22], z72 = zv[23];
    f32x2 o0 = cst[100], o1 = cst[101], o2 = cst[102];

    #pragma unroll
    for (int n = 0; n < 4; n++) {
        const f32x2* cs = cst + n * 25;
        f32x2 r0 = fma2(cs[0], z70, fma2(cs[1], z71, fma2(cs[2], z72, cs[9])));
        f32x2 r1 = fma2(cs[3], z70, fma2(cs[4], z71, fma2(cs[5], z72, cs[10])));
        f32x2 r2 = fma2(cs[6], z70, fma2(cs[7], z71, fma2(cs[8], z72, cs[11])));
        f32x2 s  = fma2(cs[12], z70, fma2(cs[13], z71, fma2(cs[14], z72, cs[15])));

        f32x2 esum = 0ULL, zb0 = 0ULL, zb1 = 0ULL, zb2 = 0ULL;
        #pragma unroll
        for (int t = 0; t < T_DIM; t++) {
            f32x2 a0 = zv[t * 3], a1 = zv[t * 3 + 1], a2 = zv[t * 3 + 2];
            f32x2 sc = fma2(r0, a0, fma2(r1, a1, fma2(r2, a2, s)));
            f32x2 e  = ex2_2(sc);   // scores tiny: no max-subtraction needed
            esum = add2(esum, e);
            zb0 = fma2(e, a0, zb0);
            zb1 = fma2(e, a1, zb1);
            zb2 = fma2(e, a2, zb2);
        }
        f32x2 inv = rcp_2(esum);
        zb0 = mul2(zb0, inv); zb1 = mul2(zb1, inv); zb2 = mul2(zb2, inv);
        o0 = fma2(cs[16], zb0, fma2(cs[17], zb1, fma2(cs[18], zb2, o0)));
        o1 = fma2(cs[19], zb0, fma2(cs[20], zb1, fma2(cs[21], zb2, o1)));
        o2 = fma2(cs[22], zb0, fma2(cs[23], zb1, fma2(cs[24], zb2, o2)));
    }

    *reinterpret_cast<f32x2*>(op)          = o0;
    *reinterpret_cast<f32x2*>(op + HW)     = o1;
    *reinterpret_cast<f32x2*>(op + 2 * HW) = o2;
}

// Fused kernel: 512 blocks x 128 threads, 2 pixel-pairs per thread.
// Pair 2's planes are L2-prefetched before pair 1's compute (zero register cost).
__global__ void __launch_bounds__(128)
fused_kernel(const float* __restrict__ z, float* __restrict__ out,
             const float* __restrict__ W_in, const float* __restrict__ b_in,
             const float* __restrict__ W_q,  const float* __restrict__ b_q,
             const float* __restrict__ W_k,  const float* __restrict__ b_k,
             const float* __restrict__ W_v,  const float* __restrict__ b_v,
             const float* __restrict__ W_o,  const float* __restrict__ b_o) {
    __shared__ float Wqs[32 * WPAD], Wks[32 * WPAD], Wvs[32 * WPAD];
    __shared__ float Wis[96], Wos[96];
    __shared__ float bis[32], bqs[32], bks[32], bvs[32], bos[3];
    __shared__ float A[32][3], Bm[32][3], Cm[32][3];
    __shared__ float aQ[32], bK[32], cV[32];
    __shared__ f32x2 cst[103];

    int tid = threadIdx.x;  // 128 threads

    // ---- stage weights into shared, fully coalesced ----
    #pragma unroll
    for (int p = 0; p < 8; p++) {
        int idx = p * 128 + tid;           // 0..1023
        int o = idx >> 5, j = idx & 31;
        Wqs[o * WPAD + j] = W_q[idx];
        Wks[o * WPAD + j] = W_k[idx];
        Wvs[o * WPAD + j] = W_v[idx];
    }
    if (tid < 96) { Wis[tid] = W_in[tid]; Wos[tid] = W_o[tid]; }
    if (tid < 32) { bis[tid] = b_in[tid]; bqs[tid] = b_q[tid];
                    bks[tid] = b_k[tid];  bvs[tid] = b_v[tid]; }
    if (tid < 3)  { bos[tid] = b_o[tid]; }
    __syncthreads();

    // ---- setup phase 1: A = W_q@W_in etc. (shared reads, conflict-free) ----
    #pragma unroll
    for (int m = 0; m < 3; m++) {
        const float* Wm = (m == 0) ? Wqs : (m == 1) ? Wks : Wvs;
        const float* bm = (m == 0) ? bqs : (m == 1) ? bks : bvs;
        if (tid < 96) {
            int o = tid & 31, i = tid >> 5;
            float s = 0.f;
            #pragma unroll
            for (int j = 0; j < 32; j++) s += Wm[o * WPAD + j] * Wis[j * 3 + i];
            if (m == 0) A[o][i] = s; else if (m == 1) Bm[o][i] = s; else Cm[o][i] = s;
        } else {
            int o = tid - 96;
            float s = bm[o];
            #pragma unroll
            for (int j = 0; j < 32; j++) s += Wm[o * WPAD + j] * bis[j];
            if (m == 0) aQ[o] = s; else if (m == 1) bK[o] = s; else cV[o] = s;
        }
    }
    __syncthreads();

    // ---- setup phase 2: fold into 103 constants ----
    const float scale = 0.3535533905932738f * 1.4426950408889634f;  // 1/sqrt(8)*log2(e)
    if (tid < 103) {
        float s = 0.f;
        if (tid >= 100) {
            int o = tid - 100;
            s = bos[o];
            #pragma unroll
            for (int r = 0; r < 32; r++) s += Wos[o * 32 + r] * cV[r];
        } else {
            int n = tid / 25, k = tid - 25 * n;
            int base = n * 8;
            if (k < 9) {
                int j = k / 3, i = k - 3 * j;
                #pragma unroll
                for (int d = 0; d < 8; d++) s += A[base + d][i] * Bm[base + d][j];
                s *= scale;
            } else if (k < 12) {
                int j = k - 9;
                #pragma unroll
                for (int d = 0; d < 8; d++) s += aQ[base + d] * Bm[base + d][j];
                s *= scale;
            } else if (k < 15) {
                int i = k - 12;
                #pragma unroll
                for (int d = 0; d < 8; d++) s += A[base + d][i] * bK[base + d];
                s *= scale;
            } else if (k == 15) {
                #pragma unroll
                for (int d = 0; d < 8; d++) s += aQ[base + d] * bK[base + d];
                s *= scale;
            } else {
                int kk = k - 16;
                int o = kk / 3, i = kk - 3 * o;
                #pragma unroll
                for (int d = 0; d < 8; d++) s += Wos[o * 32 + base + d] * Cm[base + d][i];
            }
        }
        cst[tid] = pack2(s, s);
    }
    __syncthreads();

    // Fence: keep pixel loads below the setup phase (live-range containment).
    asm volatile("" ::: "memory");

    // ---- main phase: 2 pixel-pairs per thread ----
    // Pair p0 = gid (batches 0-1), pair p1 = gid + 65536 (batches 2-3).
    int gid = blockIdx.x * 128 + tid;          // 0..65535

    int pix0 = gid << 1;
    int b0  = pix0 >> 16;
    int hw0 = pix0 & (HW - 1);
    const float* zp0 = z + (size_t)b0 * (T_DIM * C_DIM * HW) + hw0;

    int pix1 = pix0 + NPIX / 2;                // +131072 pixels = +2 batches
    int b1  = b0 + 2;
    const float* zp1 = z + (size_t)b1 * (T_DIM * C_DIM * HW) + hw0;

    // Prefetch pair 1's planes into L2 (no destination registers).
    #pragma unroll
    for (int i = 0; i < 24; i++)
        prefetch_l2(zp1 + (size_t)i * HW);

    attn_pair(zp0, out + (size_t)b0 * (3 * HW) + hw0, cst);
    attn_pair(zp1, out + (size_t)b1 * (3 * HW) + hw0, cst);
}

extern "C" void kernel_launch(void* const* d_in, const int* in_sizes, int n_in,
                              void* d_out, int out_size) {
    const float* z    = (const float*)d_in[0];
    const float* W_in = (const float*)d_in[1];
    const float* b_in = (const float*)d_in[2];
    const float* W_q  = (const float*)d_in[3];
    const float* b_q  = (const float*)d_in[4];
    const float* W_k  = (const float*)d_in[5];
    const float* b_k  = (const float*)d_in[6];
    const float* W_v  = (const float*)d_in[7];
    const float* b_v  = (const float*)d_in[8];
    const float* W_o  = (const float*)d_in[9];
    const float* b_o  = (const float*)d_in[10];
    float* out = (float*)d_out;

    fused_kernel<<<NTHREADS_TOTAL / 128, 128>>>(z, out,
                                                W_in, b_in, W_q, b_q, W_k, b_k,
                                                W_v, b_v, W_o, b_o);
}